// round 12
// baseline (speedup 1.0000x reference)
#include <cuda_runtime.h>

#define LRATE 0.25f
#define NIT 20
#define MPAD 48
#define NBLK 148
#define NTHR 384
#define NPT 10  // float4 (=2 points) per thread => 20 points/thread
#define GSTRIDE (NBLK * NTHR)

// Persistent device scratch (rewritten deterministically every launch)
__device__ float gM[NIT + 1][MPAD];
__device__ float gLam[NIT][12];
__device__ unsigned int gBar;

// single-instruction HW tanh (sm_75+); max rel err ~5e-4, fine vs 1e-3 gate
__device__ __forceinline__ float ftanh(float x) {
    float r;
    asm("tanh.approx.f32 %0, %1;" : "=f"(r) : "f"(x));
    return r;
}

__device__ __forceinline__ void sym4mv(const float* __restrict__ A, const float* v, float* y) {
#pragma unroll
    for (int r = 0; r < 4; ++r) {
        float s = 0.f;
#pragma unroll
        for (int c = 0; c < 4; ++c) s += 0.5f * (A[4 * r + c] + A[4 * c + r]) * v[c];
        y[r] = s;
    }
}
__device__ __forceinline__ void sym2mv(const float* __restrict__ A, const float* v, float* y) {
#pragma unroll
    for (int r = 0; r < 2; ++r) {
        float s = 0.f;
#pragma unroll
        for (int c = 0; c < 2; ++c) s += 0.5f * (A[2 * r + c] + A[2 * c + r]) * v[c];
        y[r] = s;
    }
}

__device__ __forceinline__ void compute_G(const float* th, const float* M,
                                          float sp0, float sp1,
                                          const float* __restrict__ invK,
                                          const float* __restrict__ invKb,
                                          float inv2K, float* G) {
    float y[4], yb[2];
    sym4mv(invK, th, y);
#pragma unroll
    for (int r = 0; r < 4; ++r) G[r] = y[r] - inv2K * M[r];
    sym2mv(invKb, th + 4, yb);
    G[4] = yb[0] - inv2K * sp0;
    G[5] = yb[1] - inv2K * sp1;
    float v2[4] = {th[6] - 1.f, th[7], th[8], th[9] - 1.f};
    sym4mv(invK, v2, y);
#pragma unroll
    for (int b = 0; b < 2; ++b)
#pragma unroll
        for (int c = 0; c < 2; ++c) {
            float pot = th[b] * M[8 + 2 * b + c] + th[2 + b] * M[8 + 4 + 2 * b + c];
            G[6 + 2 * b + c] = y[2 * b + c] - inv2K * pot;
        }
    sym2mv(invKb, th + 10, yb);
#pragma unroll
    for (int b = 0; b < 2; ++b) {
        float pot = th[b] * M[4 + b] + th[2 + b] * M[4 + 2 + b];
        G[10 + b] = yb[b] - inv2K * pot;
    }
}

__global__ void zero_kernel() {
    int t = threadIdx.x;
    if (t < (NIT + 1) * MPAD) ((float*)gM)[t] = 0.f;
    if (t == 1023) gBar = 0u;
}

// Software grid barrier (all NBLK=148 blocks co-resident: 1 block/SM, >=148 SMs)
__device__ __forceinline__ void grid_barrier(unsigned int target) {
    __syncthreads();
    if (threadIdx.x == 0) {
        asm volatile("red.release.gpu.global.add.u32 [%0], 1;" :: "l"(&gBar) : "memory");
        unsigned int v;
        do {
            asm volatile("ld.acquire.gpu.global.u32 %0, [%1];" : "=r"(v) : "l"(&gBar) : "memory");
        } while (v < target);
    }
    __syncthreads();
}

// Accumulate one point into the 28 per-pass sums
__device__ __forceinline__ void accum_pt(
    float zx, float zy, float px, float py,
    float c20, float c21, float c22, float c23, float d0, float d1,
    float t10, float t11, float t12, float t13, float* acc) {
    float u0 = fmaf(c20, zx, fmaf(c21, zy, d0));
    float u1 = fmaf(c22, zx, fmaf(c23, zy, d1));
    float h0 = ftanh(u0), h1 = ftanh(u1);
    float s0 = fmaf(-h0, h0, 1.f), s1 = fmaf(-h1, h1, 1.f);
    float s0zx = s0 * zx, s0zy = s0 * zy;
    float s1zx = s1 * zx, s1zy = s1 * zy;
    acc[0]  = fmaf(px, h0, acc[0]);
    acc[1]  = fmaf(px, h1, acc[1]);
    acc[2]  = fmaf(py, h0, acc[2]);
    acc[3]  = fmaf(py, h1, acc[3]);
    acc[4]  = fmaf(px, s0, acc[4]);
    acc[5]  = fmaf(px, s1, acc[5]);
    acc[6]  = fmaf(py, s0, acc[6]);
    acc[7]  = fmaf(py, s1, acc[7]);
    acc[8]  = fmaf(px, s0zx, acc[8]);
    acc[9]  = fmaf(px, s0zy, acc[9]);
    acc[10] = fmaf(px, s1zx, acc[10]);
    acc[11] = fmaf(px, s1zy, acc[11]);
    acc[12] = fmaf(py, s0zx, acc[12]);
    acc[13] = fmaf(py, s0zy, acc[13]);
    acc[14] = fmaf(py, s1zx, acc[14]);
    acc[15] = fmaf(py, s1zy, acc[15]);
    float w0 = fmaf(t10, px, t12 * py);
    float w1 = fmaf(t11, px, t13 * py);
    float wh0 = w0 * (h0 * s0);
    float wh1 = w1 * (h1 * s1);
    acc[16] += wh0;
    acc[17] += wh1;
    float wh0zx = wh0 * zx, wh0zy = wh0 * zy;
    float wh1zx = wh1 * zx, wh1zy = wh1 * zy;
    acc[18] += wh0zx;
    acc[19] += wh0zy;
    acc[20] += wh1zx;
    acc[21] += wh1zy;
    acc[22] = fmaf(wh0zx, zx, acc[22]);
    acc[23] = fmaf(wh0zx, zy, acc[23]);
    acc[24] = fmaf(wh0zy, zy, acc[24]);
    acc[25] = fmaf(wh1zx, zx, acc[25]);
    acc[26] = fmaf(wh1zx, zy, acc[26]);
    acc[27] = fmaf(wh1zy, zy, acc[27]);
}

// Fully fused persistent kernel (single wave, 12 warps/SM, register-resident data).
__global__ void __launch_bounds__(NTHR, 1)
mega_kernel(const float* __restrict__ inp,
            const float* __restrict__ t1i, const float* __restrict__ b1i,
            const float* __restrict__ t2i, const float* __restrict__ b2i,
            const float* __restrict__ invK, const float* __restrict__ invKb,
            float* __restrict__ out, int K) {
    __shared__ float sThAll[(NIT + 1) * 12];
    __shared__ float sLam[NIT * 12];
    __shared__ float sS4[16];   // symmetrized invK
    __shared__ float sS2[4];    // symmetrized invKb
    __shared__ float sred[28];
    __shared__ float sAcc[NTHR * 29];

    const int gtid = blockIdx.x * NTHR + threadIdx.x;
    const int npair = K >> 1;
    const float4* q4 = (const float4*)inp;
    const float4* p4 = (const float4*)(inp + 2 * (size_t)K);
    const float4* x4 = (const float4*)(inp + 4 * (size_t)K);
    const float inv2K = 0.5f / (float)K;

    if (threadIdx.x < 16)
        sS4[threadIdx.x] = 0.5f * (invK[threadIdx.x] +
                                   invK[(threadIdx.x & 3) * 4 + (threadIdx.x >> 2)]);
    else if (threadIdx.x < 20) {
        int t = threadIdx.x - 16;
        sS2[t] = 0.5f * (invKb[t] + invKb[(t & 1) * 2 + (t >> 1)]);
    }

    // ---- load this thread's 20 points into registers (zero-padded) ----
    float4 qr[NPT], pr[NPT];
    float sp0 = 0.f, sp1 = 0.f;
#pragma unroll
    for (int i = 0; i < NPT; ++i) {
        int idx = gtid + i * GSTRIDE;
        if (idx < npair) { qr[i] = q4[idx]; pr[i] = p4[idx]; }
        else { qr[i] = make_float4(0.f, 0.f, 0.f, 0.f); pr[i] = qr[i]; }
        sp0 += pr[i].x + pr[i].z;
        sp1 += pr[i].y + pr[i].w;
    }
#pragma unroll
    for (int off = 16; off > 0; off >>= 1) {
        sp0 += __shfl_down_sync(0xffffffffu, sp0, off);
        sp1 += __shfl_down_sync(0xffffffffu, sp1, off);
    }
    if ((threadIdx.x & 31) == 0) {
        atomicAdd(&gM[0][40], sp0);
        atomicAdd(&gM[0][41], sp1);
    }

    // ---- 21 passes ----
    for (int k = 0; k <= NIT; ++k) {
        // theta update, parallel across 12 threads
        if (threadIdx.x < 12) {
            int j = threadIdx.x;
            float thn;
            if (k == 0) {
                thn = (j < 4) ? t1i[j]
                    : (j < 6) ? b1i[j - 4]
                    : (j < 10) ? t2i[j - 6]
                               : b2i[j - 10];
            } else {
                const float* thp = &sThAll[12 * (k - 1)];
                const float* M = gM[k - 1];
                float G;
                if (j < 4) {
                    float y = sS4[4 * j + 0] * thp[0] + sS4[4 * j + 1] * thp[1]
                            + sS4[4 * j + 2] * thp[2] + sS4[4 * j + 3] * thp[3];
                    G = y - inv2K * M[j];
                } else if (j < 6) {
                    int r = j - 4;
                    float y = sS2[2 * r + 0] * thp[4] + sS2[2 * r + 1] * thp[5];
                    G = y - inv2K * gM[0][40 + r];
                } else if (j < 10) {
                    int r = j - 6;
                    float y = sS4[4 * r + 0] * (thp[6] - 1.f) + sS4[4 * r + 1] * thp[7]
                            + sS4[4 * r + 2] * thp[8] + sS4[4 * r + 3] * (thp[9] - 1.f);
                    int b = r >> 1, c = r & 1;
                    float pot = thp[b] * M[8 + 2 * b + c] + thp[2 + b] * M[8 + 4 + 2 * b + c];
                    G = y - inv2K * pot;
                } else {
                    int b = j - 10;
                    float y = sS2[2 * b + 0] * thp[10] + sS2[2 * b + 1] * thp[11];
                    float pot = thp[b] * M[4 + b] + thp[2 + b] * M[4 + 2 + b];
                    G = y - inv2K * pot;
                }
                thn = thp[j] - LRATE * G;
            }
            sThAll[12 * k + j] = thn;
        }
        if (threadIdx.x >= 32 && threadIdx.x < 60) sred[threadIdx.x - 32] = 0.f;
        __syncthreads();

        const float t10 = sThAll[12 * k + 0], t11 = sThAll[12 * k + 1];
        const float t12 = sThAll[12 * k + 2], t13 = sThAll[12 * k + 3];
        const float c20 = sThAll[12 * k + 6], c21 = sThAll[12 * k + 7];
        const float c22 = sThAll[12 * k + 8], c23 = sThAll[12 * k + 9];
        const float d0 = sThAll[12 * k + 10], d1 = sThAll[12 * k + 11];

        float acc[28];
#pragma unroll
        for (int j = 0; j < 28; ++j) acc[j] = 0.f;
#pragma unroll
        for (int i = 0; i < NPT; ++i) {
            accum_pt(qr[i].x, qr[i].y, pr[i].x, pr[i].y,
                     c20, c21, c22, c23, d0, d1, t10, t11, t12, t13, acc);
            accum_pt(qr[i].z, qr[i].w, pr[i].z, pr[i].w,
                     c20, c21, c22, c23, d0, d1, t10, t11, t12, t13, acc);
        }

        // smem transpose reduction (stride 29, conflict-free)
#pragma unroll
        for (int j = 0; j < 28; ++j) sAcc[threadIdx.x * 29 + j] = acc[j];
        __syncthreads();
        {
            int w = threadIdx.x >> 5;
            int lane = threadIdx.x & 31;
            if (lane < 28) {
                float s = 0.f;
                int base = (w << 5) * 29 + lane;
#pragma unroll
                for (int i = 0; i < 32; ++i) s += sAcc[base + i * 29];
                atomicAdd(&sred[lane], s);
            }
        }
        __syncthreads();
        if (threadIdx.x < 28) atomicAdd(&gM[k][threadIdx.x], sred[threadIdx.x]);

        grid_barrier((unsigned)NBLK * (unsigned)(k + 1));
    }

    // ---- backward (block 0, thread 0) ----
    if (blockIdx.x == 0 && threadIdx.x == 0) {
        float lam[12];
        compute_G(&sThAll[12 * NIT], gM[NIT], gM[0][40], gM[0][41], invK, invKb, inv2K, lam);
        for (int k = NIT - 1; k >= 0; --k) {
#pragma unroll
            for (int j = 0; j < 12; ++j) gLam[k][j] = lam[j];
            if (k > 0) {
                const float* M = gM[k];
                float y[12], t4[4], tb[2];
                sym4mv(invK, lam, t4);       y[0]=t4[0]; y[1]=t4[1]; y[2]=t4[2]; y[3]=t4[3];
                sym2mv(invKb, lam + 4, tb);  y[4]=tb[0]; y[5]=tb[1];
                sym4mv(invK, lam + 6, t4);   y[6]=t4[0]; y[7]=t4[1]; y[8]=t4[2]; y[9]=t4[3];
                sym2mv(invKb, lam + 10, tb); y[10]=tb[0]; y[11]=tb[1];

                const float* T4 = M + 16;
                const float* T5 = M + 18;
                const float* T6 = M + 22;

                float PL[12];
#pragma unroll
                for (int a = 0; a < 2; ++a)
#pragma unroll
                    for (int b = 0; b < 2; ++b)
                        PL[2 * a + b] = M[8 + 4 * a + 2 * b + 0] * lam[6 + 2 * b + 0]
                                      + M[8 + 4 * a + 2 * b + 1] * lam[6 + 2 * b + 1]
                                      + M[4 + 2 * a + b] * lam[10 + b];
                PL[4] = 0.f; PL[5] = 0.f;
#pragma unroll
                for (int b = 0; b < 2; ++b)
#pragma unroll
                    for (int c = 0; c < 2; ++c) {
                        float v = lam[b] * M[8 + 2 * b + c] + lam[2 + b] * M[8 + 4 + 2 * b + c];
                        v -= 2.f * (T6[3 * b + c + 0] * lam[6 + 2 * b + 0] +
                                    T6[3 * b + c + 1] * lam[6 + 2 * b + 1]);
                        v -= 2.f * T5[2 * b + c] * lam[10 + b];
                        PL[6 + 2 * b + c] = v;
                    }
#pragma unroll
                for (int b = 0; b < 2; ++b) {
                    float v = lam[b] * M[4 + b] + lam[2 + b] * M[4 + 2 + b];
                    v -= 2.f * (T5[2 * b + 0] * lam[6 + 2 * b + 0] +
                                T5[2 * b + 1] * lam[6 + 2 * b + 1]);
                    v -= 2.f * T4[b] * lam[10 + b];
                    PL[10 + b] = v;
                }
#pragma unroll
                for (int j = 0; j < 12; ++j) lam[j] -= LRATE * (y[j] - inv2K * PL[j]);
            }
        }
    }

    grid_barrier((unsigned)NBLK * (unsigned)(NIT + 2));

    // ---- phase C (fused): outputs for register-resident points (fully unrolled) ----
    for (int j = threadIdx.x; j < NIT * 12; j += NTHR)
        sLam[j] = ((const float*)gLam)[j];
    __syncthreads();

    float4* o4 = (float4*)out;
#pragma unroll
    for (int i = 0; i < NPT; ++i) {
        int idx = gtid + i * GSTRIDE;
        if (idx < npair) {
            float zx0 = qr[i].x, zy0 = qr[i].y, zx1 = qr[i].z, zy1 = qr[i].w;
            float px0 = pr[i].x, py0 = pr[i].y, px1 = pr[i].z, py1 = pr[i].w;
            float ax0 = 0.f, ay0 = 0.f, ax1 = 0.f, ay1 = 0.f;

            for (int kk = 0; kk < NIT; ++kk) {
                const float* th = &sThAll[12 * kk];
                const float* L = &sLam[12 * kk];
                float a0 = th[0], a1 = th[1], a2 = th[2], a3 = th[3];
                float c0 = th[6], c1 = th[7], c2 = th[8], c3 = th[9];
                float d0 = th[10], d1 = th[11];
                float l0 = L[0], l1 = L[1], l2 = L[2], l3 = L[3];
                float q0 = L[6], q1 = L[7], q2 = L[8], q3 = L[9];
                float r0 = L[10], r1 = L[11];
                {
                    float u0 = fmaf(c0, zx0, fmaf(c1, zy0, d0));
                    float u1 = fmaf(c2, zx0, fmaf(c3, zy0, d1));
                    float h0 = ftanh(u0), h1 = ftanh(u1);
                    float s0 = fmaf(-h0, h0, 1.f), s1 = fmaf(-h1, h1, 1.f);
                    float w0 = fmaf(a0, px0, a2 * py0);
                    float w1 = fmaf(a1, px0, a3 * py0);
                    float m0 = fmaf(l0, px0, l2 * py0);
                    float m1 = fmaf(l1, px0, l3 * py0);
                    float k0 = fmaf(q0, zx0, fmaf(q1, zy0, r0));
                    float k1 = fmaf(q2, zx0, fmaf(q3, zy0, r1));
                    float e0 = s0 * fmaf(-2.f * w0 * h0, k0, m0);
                    float e1 = s1 * fmaf(-2.f * w1 * h1, k1, m1);
                    float ws0 = w0 * s0, ws1 = w1 * s1;
                    ax0 = fmaf(e0, c0, fmaf(e1, c2, fmaf(q0, ws0, fmaf(q2, ws1, ax0))));
                    ay0 = fmaf(e0, c1, fmaf(e1, c3, fmaf(q1, ws0, fmaf(q3, ws1, ay0))));
                }
                {
                    float u0 = fmaf(c0, zx1, fmaf(c1, zy1, d0));
                    float u1 = fmaf(c2, zx1, fmaf(c3, zy1, d1));
                    float h0 = ftanh(u0), h1 = ftanh(u1);
                    float s0 = fmaf(-h0, h0, 1.f), s1 = fmaf(-h1, h1, 1.f);
                    float w0 = fmaf(a0, px1, a2 * py1);
                    float w1 = fmaf(a1, px1, a3 * py1);
                    float m0 = fmaf(l0, px1, l2 * py1);
                    float m1 = fmaf(l1, px1, l3 * py1);
                    float k0 = fmaf(q0, zx1, fmaf(q1, zy1, r0));
                    float k1 = fmaf(q2, zx1, fmaf(q3, zy1, r1));
                    float e0 = s0 * fmaf(-2.f * w0 * h0, k0, m0);
                    float e1 = s1 * fmaf(-2.f * w1 * h1, k1, m1);
                    float ws0 = w0 * s0, ws1 = w1 * s1;
                    ax1 = fmaf(e0, c0, fmaf(e1, c2, fmaf(q0, ws0, fmaf(q2, ws1, ax1))));
                    ay1 = fmaf(e0, c1, fmaf(e1, c3, fmaf(q1, ws0, fmaf(q3, ws1, ay1))));
                }
            }

            const float* th = &sThAll[12 * NIT];
            float a0 = th[0], a1 = th[1], a2 = th[2], a3 = th[3], b0 = th[4], b1v = th[5];
            float c0 = th[6], c1 = th[7], c2 = th[8], c3 = th[9], d0 = th[10], d1 = th[11];
            float4 xv = x4[idx];
            float4 oq, op, ox;
            {
                float u0 = fmaf(c0, zx0, fmaf(c1, zy0, d0));
                float u1 = fmaf(c2, zx0, fmaf(c3, zy0, d1));
                float h0 = ftanh(u0), h1 = ftanh(u1);
                float s0 = fmaf(-h0, h0, 1.f), s1 = fmaf(-h1, h1, 1.f);
                float w0 = fmaf(a0, px0, a2 * py0);
                float w1 = fmaf(a1, px0, a3 * py0);
                float ws0 = w0 * s0, ws1 = w1 * s1;
                oq.x = fmaf(a0, h0, fmaf(a1, h1, b0));
                oq.y = fmaf(a2, h0, fmaf(a3, h1, b1v));
                op.x = inv2K * (LRATE * ax0 - (ws0 * c0 + ws1 * c2));
                op.y = inv2K * (LRATE * ay0 - (ws0 * c1 + ws1 * c3));
            }
            {
                float u0 = fmaf(c0, zx1, fmaf(c1, zy1, d0));
                float u1 = fmaf(c2, zx1, fmaf(c3, zy1, d1));
                float h0 = ftanh(u0), h1 = ftanh(u1);
                float s0 = fmaf(-h0, h0, 1.f), s1 = fmaf(-h1, h1, 1.f);
                float w0 = fmaf(a0, px1, a2 * py1);
                float w1 = fmaf(a1, px1, a3 * py1);
                float ws0 = w0 * s0, ws1 = w1 * s1;
                oq.z = fmaf(a0, h0, fmaf(a1, h1, b0));
                oq.w = fmaf(a2, h0, fmaf(a3, h1, b1v));
                op.z = inv2K * (LRATE * ax1 - (ws0 * c0 + ws1 * c2));
                op.w = inv2K * (LRATE * ay1 - (ws0 * c1 + ws1 * c3));
            }
            {
                float v0 = fmaf(c0, xv.x, fmaf(c1, xv.y, d0));
                float v1 = fmaf(c2, xv.x, fmaf(c3, xv.y, d1));
                float g0 = ftanh(v0), g1 = ftanh(v1);
                ox.x = fmaf(a0, g0, fmaf(a1, g1, b0));
                ox.y = fmaf(a2, g0, fmaf(a3, g1, b1v));
                float v2 = fmaf(c0, xv.z, fmaf(c1, xv.w, d0));
                float v3 = fmaf(c2, xv.z, fmaf(c3, xv.w, d1));
                float g2 = ftanh(v2), g3 = ftanh(v3);
                ox.z = fmaf(a0, g2, fmaf(a1, g3, b0));
                ox.w = fmaf(a2, g2, fmaf(a3, g3, b1v));
            }
            o4[idx] = oq;
            o4[idx + npair] = op;
            o4[idx + 2 * npair] = ox;
        }
    }
}

extern "C" void kernel_launch(void* const* d_in, const int* in_sizes, int n_in,
                              void* d_out, int out_size) {
    (void)n_in; (void)out_size;
    const float* inp   = (const float*)d_in[1];
    const float* t1i   = (const float*)d_in[2];
    const float* b1i   = (const float*)d_in[3];
    const float* t2i   = (const float*)d_in[4];
    const float* b2i   = (const float*)d_in[5];
    const float* invK  = (const float*)d_in[6];
    const float* invKb = (const float*)d_in[7];
    int K = in_sizes[1] / 6;

    zero_kernel<<<1, 1024>>>();
    mega_kernel<<<NBLK, NTHR>>>(inp, t1i, b1i, t2i, b2i, invK, invKb, (float*)d_out, K);
}

// round 13
// speedup vs baseline: 1.0729x; 1.0729x over previous
#include <cuda_runtime.h>

#define LRATE 0.25f
#define NIT 20
#define MPAD 48
#define NBLK 148
#define NTHR 256
#define NPT 14  // float4 (=2 points) per thread => 28 points/thread
#define GSTRIDE (NBLK * NTHR)

// Persistent device scratch (rewritten deterministically every launch)
__device__ float gM[NIT + 1][MPAD];
__device__ unsigned int gBar;

// single-instruction HW tanh (sm_75+); max rel err ~5e-4, fine vs 1e-3 gate
__device__ __forceinline__ float ftanh(float x) {
    float r;
    asm("tanh.approx.f32 %0, %1;" : "=f"(r) : "f"(x));
    return r;
}

__device__ __forceinline__ void sym4mv(const float* __restrict__ A, const float* v, float* y) {
#pragma unroll
    for (int r = 0; r < 4; ++r) {
        float s = 0.f;
#pragma unroll
        for (int c = 0; c < 4; ++c) s += 0.5f * (A[4 * r + c] + A[4 * c + r]) * v[c];
        y[r] = s;
    }
}
__device__ __forceinline__ void sym2mv(const float* __restrict__ A, const float* v, float* y) {
#pragma unroll
    for (int r = 0; r < 2; ++r) {
        float s = 0.f;
#pragma unroll
        for (int c = 0; c < 2; ++c) s += 0.5f * (A[2 * r + c] + A[2 * c + r]) * v[c];
        y[r] = s;
    }
}

__device__ __forceinline__ void compute_G(const float* th, const float* M,
                                          float sp0, float sp1,
                                          const float* __restrict__ invK,
                                          const float* __restrict__ invKb,
                                          float inv2K, float* G) {
    float y[4], yb[2];
    sym4mv(invK, th, y);
#pragma unroll
    for (int r = 0; r < 4; ++r) G[r] = y[r] - inv2K * M[r];
    sym2mv(invKb, th + 4, yb);
    G[4] = yb[0] - inv2K * sp0;
    G[5] = yb[1] - inv2K * sp1;
    float v2[4] = {th[6] - 1.f, th[7], th[8], th[9] - 1.f};
    sym4mv(invK, v2, y);
#pragma unroll
    for (int b = 0; b < 2; ++b)
#pragma unroll
        for (int c = 0; c < 2; ++c) {
            float pot = th[b] * M[8 + 2 * b + c] + th[2 + b] * M[8 + 4 + 2 * b + c];
            G[6 + 2 * b + c] = y[2 * b + c] - inv2K * pot;
        }
    sym2mv(invKb, th + 10, yb);
#pragma unroll
    for (int b = 0; b < 2; ++b) {
        float pot = th[b] * M[4 + b] + th[2 + b] * M[4 + 2 + b];
        G[10 + b] = yb[b] - inv2K * pot;
    }
}

__global__ void zero_kernel() {
    int t = threadIdx.x;
    if (t < (NIT + 1) * MPAD) ((float*)gM)[t] = 0.f;
    if (t == 1023) gBar = 0u;
}

// Software grid barrier (all NBLK=148 blocks co-resident: 1 block/SM, >=148 SMs)
__device__ __forceinline__ void grid_barrier(unsigned int target) {
    __syncthreads();
    if (threadIdx.x == 0) {
        asm volatile("red.release.gpu.global.add.u32 [%0], 1;" :: "l"(&gBar) : "memory");
        unsigned int v;
        do {
            asm volatile("ld.acquire.gpu.global.u32 %0, [%1];" : "=r"(v) : "l"(&gBar) : "memory");
        } while (v < target);
    }
    __syncthreads();
}

// Forward-moment accumulation (16 sums)
__device__ __forceinline__ void accum_fwd(
    float zx, float zy, float px, float py,
    float c20, float c21, float c22, float c23, float d0, float d1,
    float& h0o, float& h1o, float& s0o, float& s1o, float* acc) {
    float u0 = fmaf(c20, zx, fmaf(c21, zy, d0));
    float u1 = fmaf(c22, zx, fmaf(c23, zy, d1));
    float h0 = ftanh(u0), h1 = ftanh(u1);
    float s0 = fmaf(-h0, h0, 1.f), s1 = fmaf(-h1, h1, 1.f);
    float s0zx = s0 * zx, s0zy = s0 * zy;
    float s1zx = s1 * zx, s1zy = s1 * zy;
    acc[0]  = fmaf(px, h0, acc[0]);
    acc[1]  = fmaf(px, h1, acc[1]);
    acc[2]  = fmaf(py, h0, acc[2]);
    acc[3]  = fmaf(py, h1, acc[3]);
    acc[4]  = fmaf(px, s0, acc[4]);
    acc[5]  = fmaf(px, s1, acc[5]);
    acc[6]  = fmaf(py, s0, acc[6]);
    acc[7]  = fmaf(py, s1, acc[7]);
    acc[8]  = fmaf(px, s0zx, acc[8]);
    acc[9]  = fmaf(px, s0zy, acc[9]);
    acc[10] = fmaf(px, s1zx, acc[10]);
    acc[11] = fmaf(px, s1zy, acc[11]);
    acc[12] = fmaf(py, s0zx, acc[12]);
    acc[13] = fmaf(py, s0zy, acc[13]);
    acc[14] = fmaf(py, s1zx, acc[14]);
    acc[15] = fmaf(py, s1zy, acc[15]);
    h0o = h0; h1o = h1; s0o = s0; s1o = s1;
}

__device__ __forceinline__ void accum_T(
    float zx, float zy, float px, float py,
    float h0, float h1, float s0, float s1,
    float t10, float t11, float t12, float t13, float* acc) {
    float w0 = fmaf(t10, px, t12 * py);
    float w1 = fmaf(t11, px, t13 * py);
    float wh0 = w0 * (h0 * s0);
    float wh1 = w1 * (h1 * s1);
    acc[16] += wh0;
    acc[17] += wh1;
    float wh0zx = wh0 * zx, wh0zy = wh0 * zy;
    float wh1zx = wh1 * zx, wh1zy = wh1 * zy;
    acc[18] += wh0zx;
    acc[19] += wh0zy;
    acc[20] += wh1zx;
    acc[21] += wh1zy;
    acc[22] = fmaf(wh0zx, zx, acc[22]);
    acc[23] = fmaf(wh0zx, zy, acc[23]);
    acc[24] = fmaf(wh0zy, zy, acc[24]);
    acc[25] = fmaf(wh1zx, zx, acc[25]);
    acc[26] = fmaf(wh1zx, zy, acc[26]);
    acc[27] = fmaf(wh1zy, zy, acc[27]);
}

// Fully fused persistent kernel (single wave, per-block redundant backward).
__global__ void __launch_bounds__(NTHR, 1)
mega_kernel(const float* __restrict__ inp,
            const float* __restrict__ t1i, const float* __restrict__ b1i,
            const float* __restrict__ t2i, const float* __restrict__ b2i,
            const float* __restrict__ invK, const float* __restrict__ invKb,
            float* __restrict__ out, int K) {
    __shared__ float sThAll[(NIT + 1) * 12];
    __shared__ float sLam[NIT * 12];
    __shared__ float sred[28];
    __shared__ float sAcc[NTHR * 29];

    const int gtid = blockIdx.x * NTHR + threadIdx.x;
    const int npair = K >> 1;
    const float4* q4 = (const float4*)inp;
    const float4* p4 = (const float4*)(inp + 2 * (size_t)K);
    const float4* x4 = (const float4*)(inp + 4 * (size_t)K);
    const float inv2K = 0.5f / (float)K;

    // ---- load this thread's 28 points into registers (zero-padded) ----
    float4 qr[NPT], pr[NPT];
    float sp0 = 0.f, sp1 = 0.f;
#pragma unroll
    for (int i = 0; i < NPT; ++i) {
        int idx = gtid + i * GSTRIDE;
        if (idx < npair) { qr[i] = q4[idx]; pr[i] = p4[idx]; }
        else { qr[i] = make_float4(0.f, 0.f, 0.f, 0.f); pr[i] = qr[i]; }
        sp0 += pr[i].x + pr[i].z;
        sp1 += pr[i].y + pr[i].w;
    }
#pragma unroll
    for (int off = 16; off > 0; off >>= 1) {
        sp0 += __shfl_down_sync(0xffffffffu, sp0, off);
        sp1 += __shfl_down_sync(0xffffffffu, sp1, off);
    }
    if ((threadIdx.x & 31) == 0) {
        atomicAdd(&gM[0][40], sp0);
        atomicAdd(&gM[0][41], sp1);
    }

    // ---- 21 passes ----
    for (int k = 0; k <= NIT; ++k) {
        if (threadIdx.x == 0) {
            float th[12];
            if (k == 0) {
                th[0] = t1i[0]; th[1] = t1i[1]; th[2] = t1i[2]; th[3] = t1i[3];
                th[4] = b1i[0]; th[5] = b1i[1];
                th[6] = t2i[0]; th[7] = t2i[1]; th[8] = t2i[2]; th[9] = t2i[3];
                th[10] = b2i[0]; th[11] = b2i[1];
            } else {
                float G[12];
                compute_G(&sThAll[12 * (k - 1)], gM[k - 1], gM[0][40], gM[0][41],
                          invK, invKb, inv2K, G);
#pragma unroll
                for (int j = 0; j < 12; ++j) th[j] = sThAll[12 * (k - 1) + j] - LRATE * G[j];
            }
#pragma unroll
            for (int j = 0; j < 12; ++j) sThAll[12 * k + j] = th[j];
        }
        if (threadIdx.x < 28) sred[threadIdx.x] = 0.f;
        __syncthreads();

        const float t10 = sThAll[12 * k + 0], t11 = sThAll[12 * k + 1];
        const float t12 = sThAll[12 * k + 2], t13 = sThAll[12 * k + 3];
        const float c20 = sThAll[12 * k + 6], c21 = sThAll[12 * k + 7];
        const float c22 = sThAll[12 * k + 8], c23 = sThAll[12 * k + 9];
        const float d0 = sThAll[12 * k + 10], d1 = sThAll[12 * k + 11];

        float acc[28];
#pragma unroll
        for (int j = 0; j < 28; ++j) acc[j] = 0.f;

        const bool doT = (k > 0) && (k < NIT);
        float h0, h1, s0, s1;
        if (doT) {
#pragma unroll
            for (int i = 0; i < NPT; ++i) {
                accum_fwd(qr[i].x, qr[i].y, pr[i].x, pr[i].y,
                          c20, c21, c22, c23, d0, d1, h0, h1, s0, s1, acc);
                accum_T(qr[i].x, qr[i].y, pr[i].x, pr[i].y, h0, h1, s0, s1,
                        t10, t11, t12, t13, acc);
                accum_fwd(qr[i].z, qr[i].w, pr[i].z, pr[i].w,
                          c20, c21, c22, c23, d0, d1, h0, h1, s0, s1, acc);
                accum_T(qr[i].z, qr[i].w, pr[i].z, pr[i].w, h0, h1, s0, s1,
                        t10, t11, t12, t13, acc);
            }
        } else {
#pragma unroll
            for (int i = 0; i < NPT; ++i) {
                accum_fwd(qr[i].x, qr[i].y, pr[i].x, pr[i].y,
                          c20, c21, c22, c23, d0, d1, h0, h1, s0, s1, acc);
                accum_fwd(qr[i].z, qr[i].w, pr[i].z, pr[i].w,
                          c20, c21, c22, c23, d0, d1, h0, h1, s0, s1, acc);
            }
        }

        // smem transpose reduction (stride 29, conflict-free)
        const int nred = doT ? 28 : 16;
#pragma unroll
        for (int j = 0; j < 28; ++j) sAcc[threadIdx.x * 29 + j] = acc[j];
        __syncthreads();
        {
            int w = threadIdx.x >> 5;
            int lane = threadIdx.x & 31;
            if (lane < nred) {
                float s = 0.f;
                int base = (w << 5) * 29 + lane;
#pragma unroll
                for (int i = 0; i < 32; ++i) s += sAcc[base + i * 29];
                atomicAdd(&sred[lane], s);
            }
        }
        __syncthreads();
        if (threadIdx.x < nred) atomicAdd(&gM[k][threadIdx.x], sred[threadIdx.x]);

        grid_barrier((unsigned)NBLK * (unsigned)(k + 1));
    }

    // ---- backward: EVERY block runs the 12-dim recursion redundantly ----
    if (threadIdx.x == 0) {
        float lam[12];
        compute_G(&sThAll[12 * NIT], gM[NIT], gM[0][40], gM[0][41], invK, invKb, inv2K, lam);
        for (int k = NIT - 1; k >= 0; --k) {
#pragma unroll
            for (int j = 0; j < 12; ++j) sLam[12 * k + j] = lam[j];
            if (k > 0) {
                const float* M = gM[k];
                const float* T4 = M + 16;
                const float* T5 = M + 18;
                const float* T6 = M + 22;
                float y[12], t4[4], tb[2];
                sym4mv(invK, lam, t4);       y[0]=t4[0]; y[1]=t4[1]; y[2]=t4[2]; y[3]=t4[3];
                sym2mv(invKb, lam + 4, tb);  y[4]=tb[0]; y[5]=tb[1];
                sym4mv(invK, lam + 6, t4);   y[6]=t4[0]; y[7]=t4[1]; y[8]=t4[2]; y[9]=t4[3];
                sym2mv(invKb, lam + 10, tb); y[10]=tb[0]; y[11]=tb[1];

                float PL[12];
#pragma unroll
                for (int a = 0; a < 2; ++a)
#pragma unroll
                    for (int b = 0; b < 2; ++b)
                        PL[2 * a + b] = M[8 + 4 * a + 2 * b + 0] * lam[6 + 2 * b + 0]
                                      + M[8 + 4 * a + 2 * b + 1] * lam[6 + 2 * b + 1]
                                      + M[4 + 2 * a + b] * lam[10 + b];
                PL[4] = 0.f; PL[5] = 0.f;
#pragma unroll
                for (int b = 0; b < 2; ++b)
#pragma unroll
                    for (int c = 0; c < 2; ++c) {
                        float v = lam[b] * M[8 + 2 * b + c] + lam[2 + b] * M[8 + 4 + 2 * b + c];
                        v -= 2.f * (T6[3 * b + c + 0] * lam[6 + 2 * b + 0] +
                                    T6[3 * b + c + 1] * lam[6 + 2 * b + 1]);
                        v -= 2.f * T5[2 * b + c] * lam[10 + b];
                        PL[6 + 2 * b + c] = v;
                    }
#pragma unroll
                for (int b = 0; b < 2; ++b) {
                    float v = lam[b] * M[4 + b] + lam[2 + b] * M[4 + 2 + b];
                    v -= 2.f * (T5[2 * b + 0] * lam[6 + 2 * b + 0] +
                                T5[2 * b + 1] * lam[6 + 2 * b + 1]);
                    v -= 2.f * T4[b] * lam[10 + b];
                    PL[10 + b] = v;
                }
#pragma unroll
                for (int j = 0; j < 12; ++j) lam[j] -= LRATE * (y[j] - inv2K * PL[j]);
            }
        }
    }
    __syncthreads();

    // ---- phase C (fused, kk-outer loop): theta/lambda loaded once per iteration ----
    float axA[NPT], ayA[NPT], axB[NPT], ayB[NPT];
#pragma unroll
    for (int i = 0; i < NPT; ++i) { axA[i] = 0.f; ayA[i] = 0.f; axB[i] = 0.f; ayB[i] = 0.f; }

    for (int kk = 0; kk < NIT; ++kk) {
        const float* th = &sThAll[12 * kk];
        const float* L = &sLam[12 * kk];
        float a0 = th[0], a1 = th[1], a2 = th[2], a3 = th[3];
        float c0 = th[6], c1 = th[7], c2 = th[8], c3 = th[9];
        float d0 = th[10], d1 = th[11];
        float l0 = L[0], l1 = L[1], l2 = L[2], l3 = L[3];
        float q0 = L[6], q1 = L[7], q2 = L[8], q3 = L[9];
        float r0 = L[10], r1 = L[11];
#pragma unroll
        for (int i = 0; i < NPT; ++i) {
            {
                float zx = qr[i].x, zy = qr[i].y, px = pr[i].x, py = pr[i].y;
                float u0 = fmaf(c0, zx, fmaf(c1, zy, d0));
                float u1 = fmaf(c2, zx, fmaf(c3, zy, d1));
                float h0 = ftanh(u0), h1 = ftanh(u1);
                float s0 = fmaf(-h0, h0, 1.f), s1 = fmaf(-h1, h1, 1.f);
                float w0 = fmaf(a0, px, a2 * py);
                float w1 = fmaf(a1, px, a3 * py);
                float m0 = fmaf(l0, px, l2 * py);
                float m1 = fmaf(l1, px, l3 * py);
                float k0 = fmaf(q0, zx, fmaf(q1, zy, r0));
                float k1 = fmaf(q2, zx, fmaf(q3, zy, r1));
                float e0 = s0 * fmaf(-2.f * w0 * h0, k0, m0);
                float e1 = s1 * fmaf(-2.f * w1 * h1, k1, m1);
                float ws0 = w0 * s0, ws1 = w1 * s1;
                axA[i] = fmaf(e0, c0, fmaf(e1, c2, fmaf(q0, ws0, fmaf(q2, ws1, axA[i]))));
                ayA[i] = fmaf(e0, c1, fmaf(e1, c3, fmaf(q1, ws0, fmaf(q3, ws1, ayA[i]))));
            }
            {
                float zx = qr[i].z, zy = qr[i].w, px = pr[i].z, py = pr[i].w;
                float u0 = fmaf(c0, zx, fmaf(c1, zy, d0));
                float u1 = fmaf(c2, zx, fmaf(c3, zy, d1));
                float h0 = ftanh(u0), h1 = ftanh(u1);
                float s0 = fmaf(-h0, h0, 1.f), s1 = fmaf(-h1, h1, 1.f);
                float w0 = fmaf(a0, px, a2 * py);
                float w1 = fmaf(a1, px, a3 * py);
                float m0 = fmaf(l0, px, l2 * py);
                float m1 = fmaf(l1, px, l3 * py);
                float k0 = fmaf(q0, zx, fmaf(q1, zy, r0));
                float k1 = fmaf(q2, zx, fmaf(q3, zy, r1));
                float e0 = s0 * fmaf(-2.f * w0 * h0, k0, m0);
                float e1 = s1 * fmaf(-2.f * w1 * h1, k1, m1);
                float ws0 = w0 * s0, ws1 = w1 * s1;
                axB[i] = fmaf(e0, c0, fmaf(e1, c2, fmaf(q0, ws0, fmaf(q2, ws1, axB[i]))));
                ayB[i] = fmaf(e0, c1, fmaf(e1, c3, fmaf(q1, ws0, fmaf(q3, ws1, ayB[i]))));
            }
        }
    }

    // ---- epilogue: final theta, outputs ----
    {
        const float* th = &sThAll[12 * NIT];
        float a0 = th[0], a1 = th[1], a2 = th[2], a3 = th[3], b0 = th[4], b1v = th[5];
        float c0 = th[6], c1 = th[7], c2 = th[8], c3 = th[9], d0 = th[10], d1 = th[11];
        float4* o4 = (float4*)out;
#pragma unroll
        for (int i = 0; i < NPT; ++i) {
            int idx = gtid + i * GSTRIDE;
            if (idx < npair) {
                float4 oq, op, ox;
                {
                    float zx = qr[i].x, zy = qr[i].y, px = pr[i].x, py = pr[i].y;
                    float u0 = fmaf(c0, zx, fmaf(c1, zy, d0));
                    float u1 = fmaf(c2, zx, fmaf(c3, zy, d1));
                    float h0 = ftanh(u0), h1 = ftanh(u1);
                    float s0 = fmaf(-h0, h0, 1.f), s1 = fmaf(-h1, h1, 1.f);
                    float w0 = fmaf(a0, px, a2 * py);
                    float w1 = fmaf(a1, px, a3 * py);
                    float ws0 = w0 * s0, ws1 = w1 * s1;
                    oq.x = fmaf(a0, h0, fmaf(a1, h1, b0));
                    oq.y = fmaf(a2, h0, fmaf(a3, h1, b1v));
                    op.x = inv2K * (LRATE * axA[i] - (ws0 * c0 + ws1 * c2));
                    op.y = inv2K * (LRATE * ayA[i] - (ws0 * c1 + ws1 * c3));
                }
                {
                    float zx = qr[i].z, zy = qr[i].w, px = pr[i].z, py = pr[i].w;
                    float u0 = fmaf(c0, zx, fmaf(c1, zy, d0));
                    float u1 = fmaf(c2, zx, fmaf(c3, zy, d1));
                    float h0 = ftanh(u0), h1 = ftanh(u1);
                    float s0 = fmaf(-h0, h0, 1.f), s1 = fmaf(-h1, h1, 1.f);
                    float w0 = fmaf(a0, px, a2 * py);
                    float w1 = fmaf(a1, px, a3 * py);
                    float ws0 = w0 * s0, ws1 = w1 * s1;
                    oq.z = fmaf(a0, h0, fmaf(a1, h1, b0));
                    oq.w = fmaf(a2, h0, fmaf(a3, h1, b1v));
                    op.z = inv2K * (LRATE * axB[i] - (ws0 * c0 + ws1 * c2));
                    op.w = inv2K * (LRATE * ayB[i] - (ws0 * c1 + ws1 * c3));
                }
                {
                    float4 xv = x4[idx];
                    float v0 = fmaf(c0, xv.x, fmaf(c1, xv.y, d0));
                    float v1 = fmaf(c2, xv.x, fmaf(c3, xv.y, d1));
                    float g0 = ftanh(v0), g1 = ftanh(v1);
                    ox.x = fmaf(a0, g0, fmaf(a1, g1, b0));
                    ox.y = fmaf(a2, g0, fmaf(a3, g1, b1v));
                    float v2 = fmaf(c0, xv.z, fmaf(c1, xv.w, d0));
                    float v3 = fmaf(c2, xv.z, fmaf(c3, xv.w, d1));
                    float g2 = ftanh(v2), g3 = ftanh(v3);
                    ox.z = fmaf(a0, g2, fmaf(a1, g3, b0));
                    ox.w = fmaf(a2, g2, fmaf(a3, g3, b1v));
                }
                o4[idx] = oq;
                o4[idx + npair] = op;
                o4[idx + 2 * npair] = ox;
            }
        }
    }
}

extern "C" void kernel_launch(void* const* d_in, const int* in_sizes, int n_in,
                              void* d_out, int out_size) {
    (void)n_in; (void)out_size;
    const float* inp   = (const float*)d_in[1];
    const float* t1i   = (const float*)d_in[2];
    const float* b1i   = (const float*)d_in[3];
    const float* t2i   = (const float*)d_in[4];
    const float* b2i   = (const float*)d_in[5];
    const float* invK  = (const float*)d_in[6];
    const float* invKb = (const float*)d_in[7];
    int K = in_sizes[1] / 6;

    zero_kernel<<<1, 1024>>>();
    mega_kernel<<<NBLK, NTHR>>>(inp, t1i, b1i, t2i, b2i, invK, invKb, (float*)d_out, K);
}

// round 14
// speedup vs baseline: 1.1075x; 1.0323x over previous
#include <cuda_runtime.h>

#define LRATE 0.25f
#define NIT 20
#define MPAD 48
#define NBLK 148
#define NTHR 256
#define NPT 14  // float4 (=2 points) per thread => 28 points/thread
#define NPC 7   // phase-C chunk size (NPT/2)
#define GSTRIDE (NBLK * NTHR)

// Persistent device scratch (rewritten deterministically every launch)
__device__ float gM[NIT + 1][MPAD];
__device__ unsigned int gBar;

// single-instruction HW tanh (sm_75+); max rel err ~5e-4, fine vs 1e-3 gate
__device__ __forceinline__ float ftanh(float x) {
    float r;
    asm("tanh.approx.f32 %0, %1;" : "=f"(r) : "f"(x));
    return r;
}

__device__ __forceinline__ void sym4mv(const float* __restrict__ A, const float* v, float* y) {
#pragma unroll
    for (int r = 0; r < 4; ++r) {
        float s = 0.f;
#pragma unroll
        for (int c = 0; c < 4; ++c) s += 0.5f * (A[4 * r + c] + A[4 * c + r]) * v[c];
        y[r] = s;
    }
}
__device__ __forceinline__ void sym2mv(const float* __restrict__ A, const float* v, float* y) {
#pragma unroll
    for (int r = 0; r < 2; ++r) {
        float s = 0.f;
#pragma unroll
        for (int c = 0; c < 2; ++c) s += 0.5f * (A[2 * r + c] + A[2 * c + r]) * v[c];
        y[r] = s;
    }
}

// Full G (backward recursion start; one thread per block, once)
__device__ __forceinline__ void compute_G(const float* th, const float* M,
                                          float sp0, float sp1,
                                          const float* __restrict__ invK,
                                          const float* __restrict__ invKb,
                                          float inv2K, float* G) {
    float y[4], yb[2];
    sym4mv(invK, th, y);
#pragma unroll
    for (int r = 0; r < 4; ++r) G[r] = y[r] - inv2K * M[r];
    sym2mv(invKb, th + 4, yb);
    G[4] = yb[0] - inv2K * sp0;
    G[5] = yb[1] - inv2K * sp1;
    float v2[4] = {th[6] - 1.f, th[7], th[8], th[9] - 1.f};
    sym4mv(invK, v2, y);
#pragma unroll
    for (int b = 0; b < 2; ++b)
#pragma unroll
        for (int c = 0; c < 2; ++c) {
            float pot = th[b] * M[8 + 2 * b + c] + th[2 + b] * M[8 + 4 + 2 * b + c];
            G[6 + 2 * b + c] = y[2 * b + c] - inv2K * pot;
        }
    sym2mv(invKb, th + 10, yb);
#pragma unroll
    for (int b = 0; b < 2; ++b) {
        float pot = th[b] * M[4 + b] + th[2 + b] * M[4 + 2 + b];
        G[10 + b] = yb[b] - inv2K * pot;
    }
}

__global__ void zero_kernel() {
    int t = threadIdx.x;
    if (t < (NIT + 1) * MPAD) ((float*)gM)[t] = 0.f;
    if (t == 1023) gBar = 0u;
}

// Software grid barrier (all NBLK=148 blocks co-resident: 1 block/SM, >=148 SMs)
__device__ __forceinline__ void grid_barrier(unsigned int target) {
    __syncthreads();
    if (threadIdx.x == 0) {
        asm volatile("red.release.gpu.global.add.u32 [%0], 1;" :: "l"(&gBar) : "memory");
        unsigned int v;
        do {
            asm volatile("ld.acquire.gpu.global.u32 %0, [%1];" : "=r"(v) : "l"(&gBar) : "memory");
        } while (v < target);
    }
    __syncthreads();
}

// Forward-moment accumulation (16 sums)
__device__ __forceinline__ void accum_fwd(
    float zx, float zy, float px, float py,
    float c20, float c21, float c22, float c23, float d0, float d1,
    float& h0o, float& h1o, float& s0o, float& s1o, float* acc) {
    float u0 = fmaf(c20, zx, fmaf(c21, zy, d0));
    float u1 = fmaf(c22, zx, fmaf(c23, zy, d1));
    float h0 = ftanh(u0), h1 = ftanh(u1);
    float s0 = fmaf(-h0, h0, 1.f), s1 = fmaf(-h1, h1, 1.f);
    float s0zx = s0 * zx, s0zy = s0 * zy;
    float s1zx = s1 * zx, s1zy = s1 * zy;
    acc[0]  = fmaf(px, h0, acc[0]);
    acc[1]  = fmaf(px, h1, acc[1]);
    acc[2]  = fmaf(py, h0, acc[2]);
    acc[3]  = fmaf(py, h1, acc[3]);
    acc[4]  = fmaf(px, s0, acc[4]);
    acc[5]  = fmaf(px, s1, acc[5]);
    acc[6]  = fmaf(py, s0, acc[6]);
    acc[7]  = fmaf(py, s1, acc[7]);
    acc[8]  = fmaf(px, s0zx, acc[8]);
    acc[9]  = fmaf(px, s0zy, acc[9]);
    acc[10] = fmaf(px, s1zx, acc[10]);
    acc[11] = fmaf(px, s1zy, acc[11]);
    acc[12] = fmaf(py, s0zx, acc[12]);
    acc[13] = fmaf(py, s0zy, acc[13]);
    acc[14] = fmaf(py, s1zx, acc[14]);
    acc[15] = fmaf(py, s1zy, acc[15]);
    h0o = h0; h1o = h1; s0o = s0; s1o = s1;
}

__device__ __forceinline__ void accum_T(
    float zx, float zy, float px, float py,
    float h0, float h1, float s0, float s1,
    float t10, float t11, float t12, float t13, float* acc) {
    float w0 = fmaf(t10, px, t12 * py);
    float w1 = fmaf(t11, px, t13 * py);
    float wh0 = w0 * (h0 * s0);
    float wh1 = w1 * (h1 * s1);
    acc[16] += wh0;
    acc[17] += wh1;
    float wh0zx = wh0 * zx, wh0zy = wh0 * zy;
    float wh1zx = wh1 * zx, wh1zy = wh1 * zy;
    acc[18] += wh0zx;
    acc[19] += wh0zy;
    acc[20] += wh1zx;
    acc[21] += wh1zy;
    acc[22] = fmaf(wh0zx, zx, acc[22]);
    acc[23] = fmaf(wh0zx, zy, acc[23]);
    acc[24] = fmaf(wh0zy, zy, acc[24]);
    acc[25] = fmaf(wh1zx, zx, acc[25]);
    acc[26] = fmaf(wh1zx, zy, acc[26]);
    acc[27] = fmaf(wh1zy, zy, acc[27]);
}

// Fully fused persistent kernel.
__global__ void __launch_bounds__(NTHR, 1)
mega_kernel(const float* __restrict__ inp,
            const float* __restrict__ t1i, const float* __restrict__ b1i,
            const float* __restrict__ t2i, const float* __restrict__ b2i,
            const float* __restrict__ invK, const float* __restrict__ invKb,
            float* __restrict__ out, int K) {
    __shared__ float sThAll[(NIT + 1) * 12];
    __shared__ float sLam[NIT * 12];
    __shared__ float sS4[16];   // symmetrized invK
    __shared__ float sS2[4];    // symmetrized invKb
    __shared__ float sred[28];
    __shared__ float sAcc[NTHR * 29];

    const int gtid = blockIdx.x * NTHR + threadIdx.x;
    const int npair = K >> 1;
    const float4* q4 = (const float4*)inp;
    const float4* p4 = (const float4*)(inp + 2 * (size_t)K);
    const float4* x4 = (const float4*)(inp + 4 * (size_t)K);
    const float inv2K = 0.5f / (float)K;

    if (threadIdx.x < 16)
        sS4[threadIdx.x] = 0.5f * (invK[threadIdx.x] +
                                   invK[(threadIdx.x & 3) * 4 + (threadIdx.x >> 2)]);
    else if (threadIdx.x < 20) {
        int t = threadIdx.x - 16;
        sS2[t] = 0.5f * (invKb[t] + invKb[(t & 1) * 2 + (t >> 1)]);
    }

    // ---- load this thread's 28 points into registers (zero-padded) ----
    float4 qr[NPT], pr[NPT];
    float sp0 = 0.f, sp1 = 0.f;
#pragma unroll
    for (int i = 0; i < NPT; ++i) {
        int idx = gtid + i * GSTRIDE;
        if (idx < npair) { qr[i] = q4[idx]; pr[i] = p4[idx]; }
        else { qr[i] = make_float4(0.f, 0.f, 0.f, 0.f); pr[i] = qr[i]; }
        sp0 += pr[i].x + pr[i].z;
        sp1 += pr[i].y + pr[i].w;
    }
#pragma unroll
    for (int off = 16; off > 0; off >>= 1) {
        sp0 += __shfl_down_sync(0xffffffffu, sp0, off);
        sp1 += __shfl_down_sync(0xffffffffu, sp1, off);
    }
    if ((threadIdx.x & 31) == 0) {
        atomicAdd(&gM[0][40], sp0);
        atomicAdd(&gM[0][41], sp1);
    }

    // ---- 21 passes ----
    for (int k = 0; k <= NIT; ++k) {
        // theta update, parallel across 12 threads (one independent L2 load each)
        if (threadIdx.x < 12) {
            int j = threadIdx.x;
            float thn;
            if (k == 0) {
                thn = (j < 4) ? t1i[j]
                    : (j < 6) ? b1i[j - 4]
                    : (j < 10) ? t2i[j - 6]
                               : b2i[j - 10];
            } else {
                const float* thp = &sThAll[12 * (k - 1)];
                const float* M = gM[k - 1];
                float G;
                if (j < 4) {
                    float y = sS4[4 * j + 0] * thp[0] + sS4[4 * j + 1] * thp[1]
                            + sS4[4 * j + 2] * thp[2] + sS4[4 * j + 3] * thp[3];
                    G = y - inv2K * M[j];
                } else if (j < 6) {
                    int r = j - 4;
                    float y = sS2[2 * r + 0] * thp[4] + sS2[2 * r + 1] * thp[5];
                    G = y - inv2K * gM[0][40 + r];
                } else if (j < 10) {
                    int r = j - 6;
                    float y = sS4[4 * r + 0] * (thp[6] - 1.f) + sS4[4 * r + 1] * thp[7]
                            + sS4[4 * r + 2] * thp[8] + sS4[4 * r + 3] * (thp[9] - 1.f);
                    int b = r >> 1, c = r & 1;
                    float pot = thp[b] * M[8 + 2 * b + c] + thp[2 + b] * M[8 + 4 + 2 * b + c];
                    G = y - inv2K * pot;
                } else {
                    int b = j - 10;
                    float y = sS2[2 * b + 0] * thp[10] + sS2[2 * b + 1] * thp[11];
                    float pot = thp[b] * M[4 + b] + thp[2 + b] * M[4 + 2 + b];
                    G = y - inv2K * pot;
                }
                thn = thp[j] - LRATE * G;
            }
            sThAll[12 * k + j] = thn;
        }
        if (threadIdx.x >= 32 && threadIdx.x < 60) sred[threadIdx.x - 32] = 0.f;
        __syncthreads();

        const float t10 = sThAll[12 * k + 0], t11 = sThAll[12 * k + 1];
        const float t12 = sThAll[12 * k + 2], t13 = sThAll[12 * k + 3];
        const float c20 = sThAll[12 * k + 6], c21 = sThAll[12 * k + 7];
        const float c22 = sThAll[12 * k + 8], c23 = sThAll[12 * k + 9];
        const float d0 = sThAll[12 * k + 10], d1 = sThAll[12 * k + 11];

        float acc[28];
#pragma unroll
        for (int j = 0; j < 28; ++j) acc[j] = 0.f;

        const bool doT = (k > 0) && (k < NIT);
        float h0, h1, s0, s1;
        if (doT) {
#pragma unroll
            for (int i = 0; i < NPT; ++i) {
                accum_fwd(qr[i].x, qr[i].y, pr[i].x, pr[i].y,
                          c20, c21, c22, c23, d0, d1, h0, h1, s0, s1, acc);
                accum_T(qr[i].x, qr[i].y, pr[i].x, pr[i].y, h0, h1, s0, s1,
                        t10, t11, t12, t13, acc);
                accum_fwd(qr[i].z, qr[i].w, pr[i].z, pr[i].w,
                          c20, c21, c22, c23, d0, d1, h0, h1, s0, s1, acc);
                accum_T(qr[i].z, qr[i].w, pr[i].z, pr[i].w, h0, h1, s0, s1,
                        t10, t11, t12, t13, acc);
            }
        } else {
#pragma unroll
            for (int i = 0; i < NPT; ++i) {
                accum_fwd(qr[i].x, qr[i].y, pr[i].x, pr[i].y,
                          c20, c21, c22, c23, d0, d1, h0, h1, s0, s1, acc);
                accum_fwd(qr[i].z, qr[i].w, pr[i].z, pr[i].w,
                          c20, c21, c22, c23, d0, d1, h0, h1, s0, s1, acc);
            }
        }

        // smem transpose reduction (stride 29, conflict-free)
        const int nred = doT ? 28 : 16;
#pragma unroll
        for (int j = 0; j < 28; ++j) sAcc[threadIdx.x * 29 + j] = acc[j];
        __syncthreads();
        {
            int w = threadIdx.x >> 5;
            int lane = threadIdx.x & 31;
            if (lane < nred) {
                float s = 0.f;
                int base = (w << 5) * 29 + lane;
#pragma unroll
                for (int i = 0; i < 32; ++i) s += sAcc[base + i * 29];
                atomicAdd(&sred[lane], s);
            }
        }
        __syncthreads();
        if (threadIdx.x < nred) atomicAdd(&gM[k][threadIdx.x], sred[threadIdx.x]);

        grid_barrier((unsigned)NBLK * (unsigned)(k + 1));
    }

    // ---- backward: EVERY block runs the 12-dim recursion redundantly ----
    if (threadIdx.x == 0) {
        float lam[12];
        compute_G(&sThAll[12 * NIT], gM[NIT], gM[0][40], gM[0][41], invK, invKb, inv2K, lam);
        for (int k = NIT - 1; k >= 0; --k) {
#pragma unroll
            for (int j = 0; j < 12; ++j) sLam[12 * k + j] = lam[j];
            if (k > 0) {
                const float* M = gM[k];
                const float* T4 = M + 16;
                const float* T5 = M + 18;
                const float* T6 = M + 22;
                float y[12], t4[4], tb[2];
                sym4mv(invK, lam, t4);       y[0]=t4[0]; y[1]=t4[1]; y[2]=t4[2]; y[3]=t4[3];
                sym2mv(invKb, lam + 4, tb);  y[4]=tb[0]; y[5]=tb[1];
                sym4mv(invK, lam + 6, t4);   y[6]=t4[0]; y[7]=t4[1]; y[8]=t4[2]; y[9]=t4[3];
                sym2mv(invKb, lam + 10, tb); y[10]=tb[0]; y[11]=tb[1];

                float PL[12];
#pragma unroll
                for (int a = 0; a < 2; ++a)
#pragma unroll
                    for (int b = 0; b < 2; ++b)
                        PL[2 * a + b] = M[8 + 4 * a + 2 * b + 0] * lam[6 + 2 * b + 0]
                                      + M[8 + 4 * a + 2 * b + 1] * lam[6 + 2 * b + 1]
                                      + M[4 + 2 * a + b] * lam[10 + b];
                PL[4] = 0.f; PL[5] = 0.f;
#pragma unroll
                for (int b = 0; b < 2; ++b)
#pragma unroll
                    for (int c = 0; c < 2; ++c) {
                        float v = lam[b] * M[8 + 2 * b + c] + lam[2 + b] * M[8 + 4 + 2 * b + c];
                        v -= 2.f * (T6[3 * b + c + 0] * lam[6 + 2 * b + 0] +
                                    T6[3 * b + c + 1] * lam[6 + 2 * b + 1]);
                        v -= 2.f * T5[2 * b + c] * lam[10 + b];
                        PL[6 + 2 * b + c] = v;
                    }
#pragma unroll
                for (int b = 0; b < 2; ++b) {
                    float v = lam[b] * M[4 + b] + lam[2 + b] * M[4 + 2 + b];
                    v -= 2.f * (T5[2 * b + 0] * lam[6 + 2 * b + 0] +
                                T5[2 * b + 1] * lam[6 + 2 * b + 1]);
                    v -= 2.f * T4[b] * lam[10 + b];
                    PL[10 + b] = v;
                }
#pragma unroll
                for (int j = 0; j < 12; ++j) lam[j] -= LRATE * (y[j] - inv2K * PL[j]);
            }
        }
    }
    __syncthreads();

    // ---- phase C (fused, kk-outer, two chunks of NPC to bound live registers) ----
    float4* o4 = (float4*)out;
#pragma unroll
    for (int ch = 0; ch < 2; ++ch) {
        const int base = ch * NPC;
        float axA[NPC], ayA[NPC], axB[NPC], ayB[NPC];
#pragma unroll
        for (int i = 0; i < NPC; ++i) { axA[i] = 0.f; ayA[i] = 0.f; axB[i] = 0.f; ayB[i] = 0.f; }

        for (int kk = 0; kk < NIT; ++kk) {
            const float* th = &sThAll[12 * kk];
            const float* L = &sLam[12 * kk];
            float a0 = th[0], a1 = th[1], a2 = th[2], a3 = th[3];
            float c0 = th[6], c1 = th[7], c2 = th[8], c3 = th[9];
            float d0 = th[10], d1 = th[11];
            float l0 = L[0], l1 = L[1], l2 = L[2], l3 = L[3];
            float q0 = L[6], q1 = L[7], q2 = L[8], q3 = L[9];
            float r0 = L[10], r1 = L[11];
#pragma unroll
            for (int i = 0; i < NPC; ++i) {
                const float4 qv = qr[base + i], pv = pr[base + i];
                {
                    float zx = qv.x, zy = qv.y, px = pv.x, py = pv.y;
                    float u0 = fmaf(c0, zx, fmaf(c1, zy, d0));
                    float u1 = fmaf(c2, zx, fmaf(c3, zy, d1));
                    float h0 = ftanh(u0), h1 = ftanh(u1);
                    float s0 = fmaf(-h0, h0, 1.f), s1 = fmaf(-h1, h1, 1.f);
                    float w0 = fmaf(a0, px, a2 * py);
                    float w1 = fmaf(a1, px, a3 * py);
                    float m0 = fmaf(l0, px, l2 * py);
                    float m1 = fmaf(l1, px, l3 * py);
                    float k0 = fmaf(q0, zx, fmaf(q1, zy, r0));
                    float k1 = fmaf(q2, zx, fmaf(q3, zy, r1));
                    float e0 = s0 * fmaf(-2.f * w0 * h0, k0, m0);
                    float e1 = s1 * fmaf(-2.f * w1 * h1, k1, m1);
                    float ws0 = w0 * s0, ws1 = w1 * s1;
                    axA[i] = fmaf(e0, c0, fmaf(e1, c2, fmaf(q0, ws0, fmaf(q2, ws1, axA[i]))));
                    ayA[i] = fmaf(e0, c1, fmaf(e1, c3, fmaf(q1, ws0, fmaf(q3, ws1, ayA[i]))));
                }
                {
                    float zx = qv.z, zy = qv.w, px = pv.z, py = pv.w;
                    float u0 = fmaf(c0, zx, fmaf(c1, zy, d0));
                    float u1 = fmaf(c2, zx, fmaf(c3, zy, d1));
                    float h0 = ftanh(u0), h1 = ftanh(u1);
                    float s0 = fmaf(-h0, h0, 1.f), s1 = fmaf(-h1, h1, 1.f);
                    float w0 = fmaf(a0, px, a2 * py);
                    float w1 = fmaf(a1, px, a3 * py);
                    float m0 = fmaf(l0, px, l2 * py);
                    float m1 = fmaf(l1, px, l3 * py);
                    float k0 = fmaf(q0, zx, fmaf(q1, zy, r0));
                    float k1 = fmaf(q2, zx, fmaf(q3, zy, r1));
                    float e0 = s0 * fmaf(-2.f * w0 * h0, k0, m0);
                    float e1 = s1 * fmaf(-2.f * w1 * h1, k1, m1);
                    float ws0 = w0 * s0, ws1 = w1 * s1;
                    axB[i] = fmaf(e0, c0, fmaf(e1, c2, fmaf(q0, ws0, fmaf(q2, ws1, axB[i]))));
                    ayB[i] = fmaf(e0, c1, fmaf(e1, c3, fmaf(q1, ws0, fmaf(q3, ws1, ayB[i]))));
                }
            }
        }

        // epilogue for this chunk
        const float* th = &sThAll[12 * NIT];
        float a0 = th[0], a1 = th[1], a2 = th[2], a3 = th[3], b0 = th[4], b1v = th[5];
        float c0 = th[6], c1 = th[7], c2 = th[8], c3 = th[9], d0 = th[10], d1 = th[11];
#pragma unroll
        for (int i = 0; i < NPC; ++i) {
            int idx = gtid + (base + i) * GSTRIDE;
            if (idx < npair) {
                const float4 qv = qr[base + i], pv = pr[base + i];
                float4 oq, op, ox;
                {
                    float zx = qv.x, zy = qv.y, px = pv.x, py = pv.y;
                    float u0 = fmaf(c0, zx, fmaf(c1, zy, d0));
                    float u1 = fmaf(c2, zx, fmaf(c3, zy, d1));
                    float h0 = ftanh(u0), h1 = ftanh(u1);
                    float s0 = fmaf(-h0, h0, 1.f), s1 = fmaf(-h1, h1, 1.f);
                    float w0 = fmaf(a0, px, a2 * py);
                    float w1 = fmaf(a1, px, a3 * py);
                    float ws0 = w0 * s0, ws1 = w1 * s1;
                    oq.x = fmaf(a0, h0, fmaf(a1, h1, b0));
                    oq.y = fmaf(a2, h0, fmaf(a3, h1, b1v));
                    op.x = inv2K * (LRATE * axA[i] - (ws0 * c0 + ws1 * c2));
                    op.y = inv2K * (LRATE * ayA[i] - (ws0 * c1 + ws1 * c3));
                }
                {
                    float zx = qv.z, zy = qv.w, px = pv.z, py = pv.w;
                    float u0 = fmaf(c0, zx, fmaf(c1, zy, d0));
                    float u1 = fmaf(c2, zx, fmaf(c3, zy, d1));
                    float h0 = ftanh(u0), h1 = ftanh(u1);
                    float s0 = fmaf(-h0, h0, 1.f), s1 = fmaf(-h1, h1, 1.f);
                    float w0 = fmaf(a0, px, a2 * py);
                    float w1 = fmaf(a1, px, a3 * py);
                    float ws0 = w0 * s0, ws1 = w1 * s1;
                    oq.z = fmaf(a0, h0, fmaf(a1, h1, b0));
                    oq.w = fmaf(a2, h0, fmaf(a3, h1, b1v));
                    op.z = inv2K * (LRATE * axB[i] - (ws0 * c0 + ws1 * c2));
                    op.w = inv2K * (LRATE * ayB[i] - (ws0 * c1 + ws1 * c3));
                }
                {
                    float4 xv = x4[idx];
                    float v0 = fmaf(c0, xv.x, fmaf(c1, xv.y, d0));
                    float v1 = fmaf(c2, xv.x, fmaf(c3, xv.y, d1));
                    float g0 = ftanh(v0), g1 = ftanh(v1);
                    ox.x = fmaf(a0, g0, fmaf(a1, g1, b0));
                    ox.y = fmaf(a2, g0, fmaf(a3, g1, b1v));
                    float v2 = fmaf(c0, xv.z, fmaf(c1, xv.w, d0));
                    float v3 = fmaf(c2, xv.z, fmaf(c3, xv.w, d1));
                    float g2 = ftanh(v2), g3 = ftanh(v3);
                    ox.z = fmaf(a0, g2, fmaf(a1, g3, b0));
                    ox.w = fmaf(a2, g2, fmaf(a3, g3, b1v));
                }
                o4[idx] = oq;
                o4[idx + npair] = op;
                o4[idx + 2 * npair] = ox;
            }
        }
    }
}

extern "C" void kernel_launch(void* const* d_in, const int* in_sizes, int n_in,
                              void* d_out, int out_size) {
    (void)n_in; (void)out_size;
    const float* inp   = (const float*)d_in[1];
    const float* t1i   = (const float*)d_in[2];
    const float* b1i   = (const float*)d_in[3];
    const float* t2i   = (const float*)d_in[4];
    const float* b2i   = (const float*)d_in[5];
    const float* invK  = (const float*)d_in[6];
    const float* invKb = (const float*)d_in[7];
    int K = in_sizes[1] / 6;

    zero_kernel<<<1, 1024>>>();
    mega_kernel<<<NBLK, NTHR>>>(inp, t1i, b1i, t2i, b2i, invK, invKb, (float*)d_out, K);
}

// round 15
// speedup vs baseline: 1.1081x; 1.0005x over previous
#include <cuda_runtime.h>

#define LRATE 0.25f
#define NIT 20
#define MPAD 48
#define NBLK 148
#define NTHR 256
#define NPT 14  // float4 (=2 points) per thread => 28 points/thread
#define NPC 7   // phase-C chunk size (NPT/2)
#define GSTRIDE (NBLK * NTHR)

// Persistent device scratch (rewritten deterministically every launch)
__device__ float gM[NIT + 1][MPAD];
__device__ unsigned int gBar;

// single-instruction HW tanh (sm_75+); max rel err ~5e-4, fine vs 1e-3 gate
__device__ __forceinline__ float ftanh(float x) {
    float r;
    asm("tanh.approx.f32 %0, %1;" : "=f"(r) : "f"(x));
    return r;
}

__device__ __forceinline__ void sym4mv(const float* __restrict__ A, const float* v, float* y) {
#pragma unroll
    for (int r = 0; r < 4; ++r) {
        float s = 0.f;
#pragma unroll
        for (int c = 0; c < 4; ++c) s += 0.5f * (A[4 * r + c] + A[4 * c + r]) * v[c];
        y[r] = s;
    }
}
__device__ __forceinline__ void sym2mv(const float* __restrict__ A, const float* v, float* y) {
#pragma unroll
    for (int r = 0; r < 2; ++r) {
        float s = 0.f;
#pragma unroll
        for (int c = 0; c < 2; ++c) s += 0.5f * (A[2 * r + c] + A[2 * c + r]) * v[c];
        y[r] = s;
    }
}

// Full G (used for the backward recursion start)
__device__ __forceinline__ void compute_G(const float* th, const float* M,
                                          float sp0, float sp1,
                                          const float* __restrict__ invK,
                                          const float* __restrict__ invKb,
                                          float inv2K, float* G) {
    float y[4], yb[2];
    sym4mv(invK, th, y);
#pragma unroll
    for (int r = 0; r < 4; ++r) G[r] = y[r] - inv2K * M[r];
    sym2mv(invKb, th + 4, yb);
    G[4] = yb[0] - inv2K * sp0;
    G[5] = yb[1] - inv2K * sp1;
    float v2[4] = {th[6] - 1.f, th[7], th[8], th[9] - 1.f};
    sym4mv(invK, v2, y);
#pragma unroll
    for (int b = 0; b < 2; ++b)
#pragma unroll
        for (int c = 0; c < 2; ++c) {
            float pot = th[b] * M[8 + 2 * b + c] + th[2 + b] * M[8 + 4 + 2 * b + c];
            G[6 + 2 * b + c] = y[2 * b + c] - inv2K * pot;
        }
    sym2mv(invKb, th + 10, yb);
#pragma unroll
    for (int b = 0; b < 2; ++b) {
        float pot = th[b] * M[4 + b] + th[2 + b] * M[4 + 2 + b];
        G[10 + b] = yb[b] - inv2K * pot;
    }
}

__global__ void zero_kernel() {
    int t = threadIdx.x;
    if (t < (NIT + 1) * MPAD) ((float*)gM)[t] = 0.f;
    if (t == 1023) gBar = 0u;
}

// Software grid barrier (all NBLK=148 blocks co-resident: 1 block/SM, >=148 SMs)
__device__ __forceinline__ void grid_barrier(unsigned int target) {
    __syncthreads();
    if (threadIdx.x == 0) {
        asm volatile("red.release.gpu.global.add.u32 [%0], 1;" :: "l"(&gBar) : "memory");
        unsigned int v;
        do {
            asm volatile("ld.acquire.gpu.global.u32 %0, [%1];" : "=r"(v) : "l"(&gBar) : "memory");
        } while (v < target);
    }
    __syncthreads();
}

// Fused per-point accumulation: 16 fwd moments, optionally + 12 contracted T's
template <bool DOT>
__device__ __forceinline__ void accum_pt(
    float zx, float zy, float px, float py,
    float c20, float c21, float c22, float c23, float d0, float d1,
    float t10, float t11, float t12, float t13, float* acc) {
    float u0 = fmaf(c20, zx, fmaf(c21, zy, d0));
    float u1 = fmaf(c22, zx, fmaf(c23, zy, d1));
    float h0 = ftanh(u0), h1 = ftanh(u1);
    float s0 = fmaf(-h0, h0, 1.f), s1 = fmaf(-h1, h1, 1.f);
    float s0zx = s0 * zx, s0zy = s0 * zy;
    float s1zx = s1 * zx, s1zy = s1 * zy;
    acc[0]  = fmaf(px, h0, acc[0]);
    acc[1]  = fmaf(px, h1, acc[1]);
    acc[2]  = fmaf(py, h0, acc[2]);
    acc[3]  = fmaf(py, h1, acc[3]);
    acc[4]  = fmaf(px, s0, acc[4]);
    acc[5]  = fmaf(px, s1, acc[5]);
    acc[6]  = fmaf(py, s0, acc[6]);
    acc[7]  = fmaf(py, s1, acc[7]);
    acc[8]  = fmaf(px, s0zx, acc[8]);
    acc[9]  = fmaf(px, s0zy, acc[9]);
    acc[10] = fmaf(px, s1zx, acc[10]);
    acc[11] = fmaf(px, s1zy, acc[11]);
    acc[12] = fmaf(py, s0zx, acc[12]);
    acc[13] = fmaf(py, s0zy, acc[13]);
    acc[14] = fmaf(py, s1zx, acc[14]);
    acc[15] = fmaf(py, s1zy, acc[15]);
    if (DOT) {
        float w0 = fmaf(t10, px, t12 * py);
        float w1 = fmaf(t11, px, t13 * py);
        float wh0 = w0 * (h0 * s0);
        float wh1 = w1 * (h1 * s1);
        acc[16] += wh0;
        acc[17] += wh1;
        float wh0zx = wh0 * zx, wh0zy = wh0 * zy;
        float wh1zx = wh1 * zx, wh1zy = wh1 * zy;
        acc[18] += wh0zx;
        acc[19] += wh0zy;
        acc[20] += wh1zx;
        acc[21] += wh1zy;
        acc[22] = fmaf(wh0zx, zx, acc[22]);
        acc[23] = fmaf(wh0zx, zy, acc[23]);
        acc[24] = fmaf(wh0zy, zy, acc[24]);
        acc[25] = fmaf(wh1zx, zx, acc[25]);
        acc[26] = fmaf(wh1zx, zy, acc[26]);
        acc[27] = fmaf(wh1zy, zy, acc[27]);
    }
}

// Fully fused persistent kernel.
__global__ void __launch_bounds__(NTHR, 1)
mega_kernel(const float* __restrict__ inp,
            const float* __restrict__ t1i, const float* __restrict__ b1i,
            const float* __restrict__ t2i, const float* __restrict__ b2i,
            const float* __restrict__ invK, const float* __restrict__ invKb,
            float* __restrict__ out, int K) {
    __shared__ float sThAll[(NIT + 1) * 12];
    __shared__ float sLam[NIT * 12];
    __shared__ float sS4[16];   // symmetrized invK
    __shared__ float sS2[4];    // symmetrized invKb
    __shared__ float sred[28];
    __shared__ float sAcc[NTHR * 29];

    const int gtid = blockIdx.x * NTHR + threadIdx.x;
    const int npair = K >> 1;
    const float4* q4 = (const float4*)inp;
    const float4* p4 = (const float4*)(inp + 2 * (size_t)K);
    const float4* x4 = (const float4*)(inp + 4 * (size_t)K);
    const float inv2K = 0.5f / (float)K;

    if (threadIdx.x < 16)
        sS4[threadIdx.x] = 0.5f * (invK[threadIdx.x] +
                                   invK[(threadIdx.x & 3) * 4 + (threadIdx.x >> 2)]);
    else if (threadIdx.x < 20) {
        int t = threadIdx.x - 16;
        sS2[t] = 0.5f * (invKb[t] + invKb[(t & 1) * 2 + (t >> 1)]);
    }

    // ---- load this thread's 28 points into registers (zero-padded) ----
    float4 qr[NPT], pr[NPT];
    float sp0 = 0.f, sp1 = 0.f;
#pragma unroll
    for (int i = 0; i < NPT; ++i) {
        int idx = gtid + i * GSTRIDE;
        if (idx < npair) { qr[i] = q4[idx]; pr[i] = p4[idx]; }
        else { qr[i] = make_float4(0.f, 0.f, 0.f, 0.f); pr[i] = qr[i]; }
        sp0 += pr[i].x + pr[i].z;
        sp1 += pr[i].y + pr[i].w;
    }
#pragma unroll
    for (int off = 16; off > 0; off >>= 1) {
        sp0 += __shfl_down_sync(0xffffffffu, sp0, off);
        sp1 += __shfl_down_sync(0xffffffffu, sp1, off);
    }
    if ((threadIdx.x & 31) == 0) {
        atomicAdd(&gM[0][40], sp0);
        atomicAdd(&gM[0][41], sp1);
    }

    // ---- 21 passes ----
    for (int k = 0; k <= NIT; ++k) {
        // theta update, parallel across 12 threads (one independent L2 load each)
        if (threadIdx.x < 12) {
            int j = threadIdx.x;
            float thn;
            if (k == 0) {
                thn = (j < 4) ? t1i[j]
                    : (j < 6) ? b1i[j - 4]
                    : (j < 10) ? t2i[j - 6]
                               : b2i[j - 10];
            } else {
                const float* thp = &sThAll[12 * (k - 1)];
                const float* M = gM[k - 1];
                float G;
                if (j < 4) {
                    float y = sS4[4 * j + 0] * thp[0] + sS4[4 * j + 1] * thp[1]
                            + sS4[4 * j + 2] * thp[2] + sS4[4 * j + 3] * thp[3];
                    G = y - inv2K * M[j];
                } else if (j < 6) {
                    int r = j - 4;
                    float y = sS2[2 * r + 0] * thp[4] + sS2[2 * r + 1] * thp[5];
                    G = y - inv2K * gM[0][40 + r];
                } else if (j < 10) {
                    int r = j - 6;
                    float y = sS4[4 * r + 0] * (thp[6] - 1.f) + sS4[4 * r + 1] * thp[7]
                            + sS4[4 * r + 2] * thp[8] + sS4[4 * r + 3] * (thp[9] - 1.f);
                    int b = r >> 1, c = r & 1;
                    float pot = thp[b] * M[8 + 2 * b + c] + thp[2 + b] * M[8 + 4 + 2 * b + c];
                    G = y - inv2K * pot;
                } else {
                    int b = j - 10;
                    float y = sS2[2 * b + 0] * thp[10] + sS2[2 * b + 1] * thp[11];
                    float pot = thp[b] * M[4 + b] + thp[2 + b] * M[4 + 2 + b];
                    G = y - inv2K * pot;
                }
                thn = thp[j] - LRATE * G;
            }
            sThAll[12 * k + j] = thn;
        }
        if (threadIdx.x >= 32 && threadIdx.x < 60) sred[threadIdx.x - 32] = 0.f;
        __syncthreads();

        const float t10 = sThAll[12 * k + 0], t11 = sThAll[12 * k + 1];
        const float t12 = sThAll[12 * k + 2], t13 = sThAll[12 * k + 3];
        const float c20 = sThAll[12 * k + 6], c21 = sThAll[12 * k + 7];
        const float c22 = sThAll[12 * k + 8], c23 = sThAll[12 * k + 9];
        const float d0 = sThAll[12 * k + 10], d1 = sThAll[12 * k + 11];

        float acc[28];
#pragma unroll
        for (int j = 0; j < 28; ++j) acc[j] = 0.f;

        const bool doT = (k > 0) && (k < NIT);
        if (doT) {
#pragma unroll
            for (int i = 0; i < NPT; ++i) {
                accum_pt<true>(qr[i].x, qr[i].y, pr[i].x, pr[i].y,
                               c20, c21, c22, c23, d0, d1, t10, t11, t12, t13, acc);
                accum_pt<true>(qr[i].z, qr[i].w, pr[i].z, pr[i].w,
                               c20, c21, c22, c23, d0, d1, t10, t11, t12, t13, acc);
            }
        } else {
#pragma unroll
            for (int i = 0; i < NPT; ++i) {
                accum_pt<false>(qr[i].x, qr[i].y, pr[i].x, pr[i].y,
                                c20, c21, c22, c23, d0, d1, t10, t11, t12, t13, acc);
                accum_pt<false>(qr[i].z, qr[i].w, pr[i].z, pr[i].w,
                                c20, c21, c22, c23, d0, d1, t10, t11, t12, t13, acc);
            }
        }

        // smem transpose reduction (stride 29, conflict-free)
        const int nred = doT ? 28 : 16;
#pragma unroll
        for (int j = 0; j < 28; ++j) sAcc[threadIdx.x * 29 + j] = acc[j];
        __syncthreads();
        {
            int w = threadIdx.x >> 5;
            int lane = threadIdx.x & 31;
            if (lane < nred) {
                float s = 0.f;
                int base = (w << 5) * 29 + lane;
#pragma unroll
                for (int i = 0; i < 32; ++i) s += sAcc[base + i * 29];
                atomicAdd(&sred[lane], s);
            }
        }
        __syncthreads();
        if (threadIdx.x < nred) atomicAdd(&gM[k][threadIdx.x], sred[threadIdx.x]);

        grid_barrier((unsigned)NBLK * (unsigned)(k + 1));
    }

    // ---- backward: EVERY block runs the 12-dim recursion redundantly ----
    if (threadIdx.x == 0) {
        float lam[12];
        compute_G(&sThAll[12 * NIT], gM[NIT], gM[0][40], gM[0][41], invK, invKb, inv2K, lam);
        for (int k = NIT - 1; k >= 0; --k) {
#pragma unroll
            for (int j = 0; j < 12; ++j) sLam[12 * k + j] = lam[j];
            if (k > 0) {
                const float* M = gM[k];
                const float* T4 = M + 16;
                const float* T5 = M + 18;
                const float* T6 = M + 22;
                float y[12], t4[4], tb[2];
                sym4mv(invK, lam, t4);       y[0]=t4[0]; y[1]=t4[1]; y[2]=t4[2]; y[3]=t4[3];
                sym2mv(invKb, lam + 4, tb);  y[4]=tb[0]; y[5]=tb[1];
                sym4mv(invK, lam + 6, t4);   y[6]=t4[0]; y[7]=t4[1]; y[8]=t4[2]; y[9]=t4[3];
                sym2mv(invKb, lam + 10, tb); y[10]=tb[0]; y[11]=tb[1];

                float PL[12];
#pragma unroll
                for (int a = 0; a < 2; ++a)
#pragma unroll
                    for (int b = 0; b < 2; ++b)
                        PL[2 * a + b] = M[8 + 4 * a + 2 * b + 0] * lam[6 + 2 * b + 0]
                                      + M[8 + 4 * a + 2 * b + 1] * lam[6 + 2 * b + 1]
                                      + M[4 + 2 * a + b] * lam[10 + b];
                PL[4] = 0.f; PL[5] = 0.f;
#pragma unroll
                for (int b = 0; b < 2; ++b)
#pragma unroll
                    for (int c = 0; c < 2; ++c) {
                        float v = lam[b] * M[8 + 2 * b + c] + lam[2 + b] * M[8 + 4 + 2 * b + c];
                        v -= 2.f * (T6[3 * b + c + 0] * lam[6 + 2 * b + 0] +
                                    T6[3 * b + c + 1] * lam[6 + 2 * b + 1]);
                        v -= 2.f * T5[2 * b + c] * lam[10 + b];
                        PL[6 + 2 * b + c] = v;
                    }
#pragma unroll
                for (int b = 0; b < 2; ++b) {
                    float v = lam[b] * M[4 + b] + lam[2 + b] * M[4 + 2 + b];
                    v -= 2.f * (T5[2 * b + 0] * lam[6 + 2 * b + 0] +
                                T5[2 * b + 1] * lam[6 + 2 * b + 1]);
                    v -= 2.f * T4[b] * lam[10 + b];
                    PL[10 + b] = v;
                }
#pragma unroll
                for (int j = 0; j < 12; ++j) lam[j] -= LRATE * (y[j] - inv2K * PL[j]);
            }
        }
    }
    __syncthreads();

    // ---- phase C (fused, kk-outer, two chunks; x prefetched per chunk) ----
    float4* o4 = (float4*)out;
#pragma unroll
    for (int ch = 0; ch < 2; ++ch) {
        const int base = ch * NPC;
        float axA[NPC], ayA[NPC], axB[NPC], ayB[NPC];
        float4 xv[NPC];
#pragma unroll
        for (int i = 0; i < NPC; ++i) {
            axA[i] = 0.f; ayA[i] = 0.f; axB[i] = 0.f; ayB[i] = 0.f;
            int idx = gtid + (base + i) * GSTRIDE;
            xv[i] = (idx < npair) ? x4[idx] : make_float4(0.f, 0.f, 0.f, 0.f);
        }

        for (int kk = 0; kk < NIT; ++kk) {
            const float* th = &sThAll[12 * kk];
            const float* L = &sLam[12 * kk];
            float a0 = th[0], a1 = th[1], a2 = th[2], a3 = th[3];
            float c0 = th[6], c1 = th[7], c2 = th[8], c3 = th[9];
            float d0 = th[10], d1 = th[11];
            float l0 = L[0], l1 = L[1], l2 = L[2], l3 = L[3];
            float q0 = L[6], q1 = L[7], q2 = L[8], q3 = L[9];
            float r0 = L[10], r1 = L[11];
#pragma unroll
            for (int i = 0; i < NPC; ++i) {
                const float4 qv = qr[base + i], pv = pr[base + i];
                {
                    float zx = qv.x, zy = qv.y, px = pv.x, py = pv.y;
                    float u0 = fmaf(c0, zx, fmaf(c1, zy, d0));
                    float u1 = fmaf(c2, zx, fmaf(c3, zy, d1));
                    float h0 = ftanh(u0), h1 = ftanh(u1);
                    float s0 = fmaf(-h0, h0, 1.f), s1 = fmaf(-h1, h1, 1.f);
                    float w0 = fmaf(a0, px, a2 * py);
                    float w1 = fmaf(a1, px, a3 * py);
                    float m0 = fmaf(l0, px, l2 * py);
                    float m1 = fmaf(l1, px, l3 * py);
                    float k0 = fmaf(q0, zx, fmaf(q1, zy, r0));
                    float k1 = fmaf(q2, zx, fmaf(q3, zy, r1));
                    float e0 = s0 * fmaf(-2.f * w0 * h0, k0, m0);
                    float e1 = s1 * fmaf(-2.f * w1 * h1, k1, m1);
                    float ws0 = w0 * s0, ws1 = w1 * s1;
                    axA[i] = fmaf(e0, c0, fmaf(e1, c2, fmaf(q0, ws0, fmaf(q2, ws1, axA[i]))));
                    ayA[i] = fmaf(e0, c1, fmaf(e1, c3, fmaf(q1, ws0, fmaf(q3, ws1, ayA[i]))));
                }
                {
                    float zx = qv.z, zy = qv.w, px = pv.z, py = pv.w;
                    float u0 = fmaf(c0, zx, fmaf(c1, zy, d0));
                    float u1 = fmaf(c2, zx, fmaf(c3, zy, d1));
                    float h0 = ftanh(u0), h1 = ftanh(u1);
                    float s0 = fmaf(-h0, h0, 1.f), s1 = fmaf(-h1, h1, 1.f);
                    float w0 = fmaf(a0, px, a2 * py);
                    float w1 = fmaf(a1, px, a3 * py);
                    float m0 = fmaf(l0, px, l2 * py);
                    float m1 = fmaf(l1, px, l3 * py);
                    float k0 = fmaf(q0, zx, fmaf(q1, zy, r0));
                    float k1 = fmaf(q2, zx, fmaf(q3, zy, r1));
                    float e0 = s0 * fmaf(-2.f * w0 * h0, k0, m0);
                    float e1 = s1 * fmaf(-2.f * w1 * h1, k1, m1);
                    float ws0 = w0 * s0, ws1 = w1 * s1;
                    axB[i] = fmaf(e0, c0, fmaf(e1, c2, fmaf(q0, ws0, fmaf(q2, ws1, axB[i]))));
                    ayB[i] = fmaf(e0, c1, fmaf(e1, c3, fmaf(q1, ws0, fmaf(q3, ws1, ayB[i]))));
                }
            }
        }

        // epilogue for this chunk
        const float* th = &sThAll[12 * NIT];
        float a0 = th[0], a1 = th[1], a2 = th[2], a3 = th[3], b0 = th[4], b1v = th[5];
        float c0 = th[6], c1 = th[7], c2 = th[8], c3 = th[9], d0 = th[10], d1 = th[11];
#pragma unroll
        for (int i = 0; i < NPC; ++i) {
            int idx = gtid + (base + i) * GSTRIDE;
            if (idx < npair) {
                const float4 qv = qr[base + i], pv = pr[base + i];
                float4 oq, op, ox;
                {
                    float zx = qv.x, zy = qv.y, px = pv.x, py = pv.y;
                    float u0 = fmaf(c0, zx, fmaf(c1, zy, d0));
                    float u1 = fmaf(c2, zx, fmaf(c3, zy, d1));
                    float h0 = ftanh(u0), h1 = ftanh(u1);
                    float s0 = fmaf(-h0, h0, 1.f), s1 = fmaf(-h1, h1, 1.f);
                    float w0 = fmaf(a0, px, a2 * py);
                    float w1 = fmaf(a1, px, a3 * py);
                    float ws0 = w0 * s0, ws1 = w1 * s1;
                    oq.x = fmaf(a0, h0, fmaf(a1, h1, b0));
                    oq.y = fmaf(a2, h0, fmaf(a3, h1, b1v));
                    op.x = inv2K * (LRATE * axA[i] - (ws0 * c0 + ws1 * c2));
                    op.y = inv2K * (LRATE * ayA[i] - (ws0 * c1 + ws1 * c3));
                }
                {
                    float zx = qv.z, zy = qv.w, px = pv.z, py = pv.w;
                    float u0 = fmaf(c0, zx, fmaf(c1, zy, d0));
                    float u1 = fmaf(c2, zx, fmaf(c3, zy, d1));
                    float h0 = ftanh(u0), h1 = ftanh(u1);
                    float s0 = fmaf(-h0, h0, 1.f), s1 = fmaf(-h1, h1, 1.f);
                    float w0 = fmaf(a0, px, a2 * py);
                    float w1 = fmaf(a1, px, a3 * py);
                    float ws0 = w0 * s0, ws1 = w1 * s1;
                    oq.z = fmaf(a0, h0, fmaf(a1, h1, b0));
                    oq.w = fmaf(a2, h0, fmaf(a3, h1, b1v));
                    op.z = inv2K * (LRATE * axB[i] - (ws0 * c0 + ws1 * c2));
                    op.w = inv2K * (LRATE * ayB[i] - (ws0 * c1 + ws1 * c3));
                }
                {
                    float v0 = fmaf(c0, xv[i].x, fmaf(c1, xv[i].y, d0));
                    float v1 = fmaf(c2, xv[i].x, fmaf(c3, xv[i].y, d1));
                    float g0 = ftanh(v0), g1 = ftanh(v1);
                    ox.x = fmaf(a0, g0, fmaf(a1, g1, b0));
                    ox.y = fmaf(a2, g0, fmaf(a3, g1, b1v));
                    float v2 = fmaf(c0, xv[i].z, fmaf(c1, xv[i].w, d0));
                    float v3 = fmaf(c2, xv[i].z, fmaf(c3, xv[i].w, d1));
                    float g2 = ftanh(v2), g3 = ftanh(v3);
                    ox.z = fmaf(a0, g2, fmaf(a1, g3, b0));
                    ox.w = fmaf(a2, g2, fmaf(a3, g3, b1v));
                }
                o4[idx] = oq;
                o4[idx + npair] = op;
                o4[idx + 2 * npair] = ox;
            }
        }
    }
}

extern "C" void kernel_launch(void* const* d_in, const int* in_sizes, int n_in,
                              void* d_out, int out_size) {
    (void)n_in; (void)out_size;
    const float* inp   = (const float*)d_in[1];
    const float* t1i   = (const float*)d_in[2];
    const float* b1i   = (const float*)d_in[3];
    const float* t2i   = (const float*)d_in[4];
    const float* b2i   = (const float*)d_in[5];
    const float* invK  = (const float*)d_in[6];
    const float* invKb = (const float*)d_in[7];
    int K = in_sizes[1] / 6;

    zero_kernel<<<1, 1024>>>();
    mega_kernel<<<NBLK, NTHR>>>(inp, t1i, b1i, t2i, b2i, invK, invKb, (float*)d_out, K);
}